// round 15
// baseline (speedup 1.0000x reference)
#include <cuda_runtime.h>
#include <cuda_fp16.h>
#include <cstdint>
#include <math.h>

#define kVocab 50000
#define kEmbed 300
#define kEmbP  320
#define kUnits 512
#define kT 128
#define kB 512
#define kG 2048

// ---------------- global scratch ----------------
__device__ float g_zpre[(size_t)kB * kT * kG];
__device__ unsigned g_bar[8];
// U^T gate-interleaved fp16, resident-layout: [nt(16)][row n'(128) x 1024B swizzled rows]
__device__ __align__(128) __half g_ur[16 * 128 * kUnits];
// h fp16 exchange staging (used by fallback path + initial h0), double buffered
__device__ __align__(128) __half g_hx[2][8 * 64 * kUnits];
__device__ __align__(128) __half g_emb_hi[(size_t)kVocab * kEmbP];
__device__ __align__(128) __half g_emb_lo[(size_t)kVocab * kEmbP];
__device__ __align__(128) __half g_wt[kG * kEmbP];

// ---------------- helpers ----------------
__device__ __forceinline__ uint32_t smem_u32(const void* p) {
    uint32_t a;
    asm("{ .reg .u64 t; cvta.to.shared.u64 t, %1; cvt.u32.u64 %0, t; }" : "=r"(a) : "l"(p));
    return a;
}
#define CP_ASYNC16(dst, src) \
    asm volatile("cp.async.cg.shared.global [%0], [%1], 16;" :: "r"(dst), "l"(src) : "memory")
#define CP_COMMIT() asm volatile("cp.async.commit_group;" ::: "memory")
#define CP_WAIT0()  asm volatile("cp.async.wait_group 0;" ::: "memory")

#define MBAR_INIT(a, c) \
    asm volatile("mbarrier.init.shared.b64 [%0], %1;" :: "r"(a), "r"(c) : "memory")
#define MBAR_EXPECT_TX(a, bytes) \
    asm volatile("mbarrier.arrive.expect_tx.shared.b64 _, [%0], %1;" :: "r"(a), "r"(bytes) : "memory")
#define TMA_BULK(dst, src, sz, mbar) \
    asm volatile("cp.async.bulk.shared::cta.global.mbarrier::complete_tx::bytes [%0], [%1], %2, [%3];" \
        :: "r"(dst), "l"(src), "r"(sz), "r"(mbar) : "memory")
#define MBAR_WAIT(a, par) do { \
    uint32_t _m = (a), _p = (par), _d; \
    asm volatile("{ .reg .pred p; mbarrier.try_wait.parity.acquire.cta.shared::cta.b64 p, [%1], %2; selp.b32 %0,1,0,p; }" \
        : "=r"(_d) : "r"(_m), "r"(_p) : "memory"); \
    if (!_d) { \
        asm volatile("{ .reg .pred P1; WL%=: mbarrier.try_wait.parity.acquire.cta.shared::cta.b64 P1, [%0], %1, 0x989680; @P1 bra.uni WD%=; bra.uni WL%=; WD%=: }" \
            :: "r"(_m), "r"(_p) : "memory"); \
    } } while (0)

#define CLUSTER_ARRIVE() asm volatile("barrier.cluster.arrive.aligned;" ::: "memory")
#define CLUSTER_WAIT()   asm volatile("barrier.cluster.wait.aligned;" ::: "memory")

__device__ __forceinline__ uint32_t mapa_rank(uint32_t addr, uint32_t rank) {
    uint32_t r;
    asm("mapa.shared::cluster.u32 %0, %1, %2;" : "=r"(r) : "r"(addr), "r"(rank));
    return r;
}
#define ST_CLUSTER128(addr, v) \
    asm volatile("st.shared::cluster.v4.b32 [%0], {%1,%2,%3,%4};" \
        :: "r"(addr), "r"((v).x), "r"((v).y), "r"((v).z), "r"((v).w) : "memory")

#define LDMATRIX_X4(r0, r1, r2, r3, addr) \
    asm volatile("ldmatrix.sync.aligned.m8n8.x4.shared.b16 {%0,%1,%2,%3}, [%4];" \
        : "=r"(r0), "=r"(r1), "=r"(r2), "=r"(r3) : "r"(addr))

#define MMA_F16(c0, c1, c2, c3, a0, a1, a2, a3, b0, b1) \
    asm volatile("mma.sync.aligned.m16n8k16.row.col.f32.f16.f16.f32 " \
        "{%0,%1,%2,%3}, {%4,%5,%6,%7}, {%8,%9}, {%0,%1,%2,%3};" \
        : "+f"(c0), "+f"(c1), "+f"(c2), "+f"(c3) \
        : "r"(a0), "r"(a1), "r"(a2), "r"(a3), "r"(b0), "r"(b1))

__device__ __forceinline__ float fast_ex2(float x) { float y; asm("ex2.approx.ftz.f32 %0, %1;" : "=f"(y) : "f"(x)); return y; }
__device__ __forceinline__ float fast_sig(float x) { return __fdividef(1.f, 1.f + fast_ex2(-1.4426950408889634f * x)); }
__device__ __forceinline__ float fast_tanh(float x) {
    float ax = fabsf(x);
    float e = fast_ex2(-2.8853900817779268f * ax);
    float t = __fdividef(1.f - e, 1.f + e);
    return copysignf(t, x);
}
__device__ __forceinline__ void split_f16(float v, __half& hi, __half& lo) {
    hi = __float2half_rn(v);
    lo = __float2half_rn(v - __half2float(hi));
}

// ---------------- prep (U/h0 writes vectorized to uint4) ----------------
__global__ __launch_bounds__(128) void prep_kernel(const float* __restrict__ U,
                                                   const float* __restrict__ h0,
                                                   const float* __restrict__ W,
                                                   const float* __restrict__ emb) {
    int blk = blockIdx.x;
    if (blk == 0 && threadIdx.x < 8) g_bar[threadIdx.x] = 0;
    if (blk < kG) {                       // U^T row n'=u*4+g -> resident layout, 16B stores
        int np = blk;
        int n = (np & 3) * kUnits + (np >> 2);
        int nt = np >> 7, rl = np & 127;
        for (int q = threadIdx.x; q < 64; q += 128) {
            __half tmp[8];
#pragma unroll
            for (int ln = 0; ln < 8; ln++)
                tmp[ln] = __float2half_rn(__ldg(U + (size_t)(q * 8 + ln) * kG + n));
            size_t base = (size_t)nt * 65536 + rl * 512 + ((q & 56) | ((q ^ rl) & 7)) * 8;
            *(uint4*)&g_ur[base] = *(uint4*)tmp;
        }
    } else if (blk < kG + 8) {            // h0 -> swizzled rows, 16B stores
        int mt = blk - kG;
        int r0 = mt * 64;
        for (int i = threadIdx.x; i < 4096; i += 128) {
            int rb = i >> 6, q = i & 63;
            __half tmp[8];
#pragma unroll
            for (int ln = 0; ln < 8; ln++)
                tmp[ln] = __float2half_rn(__ldg(h0 + (size_t)(r0 + rb) * kUnits + q * 8 + ln));
            size_t base = (size_t)mt * 32768 + rb * 512 + ((q & 56) | ((q ^ rb) & 7)) * 8;
            *(uint4*)&g_hx[0][base] = *(uint4*)tmp;
        }
    } else if (blk < kG + 8 + kG) {
        int n = blk - kG - 8;
        for (int k = threadIdx.x; k < kEmbP; k += 128) {
            float v = (k < kEmbed) ? __ldg(W + (size_t)k * kG + n) : 0.f;
            g_wt[n * kEmbP + k] = __float2half_rn(v);
        }
    } else {
        int r0 = (blk - kG - 8 - kG) * 8;
        for (int rr = 0; rr < 8; rr++) {
            int row = r0 + rr;
            if (row >= kVocab) break;
            for (int k = threadIdx.x; k < kEmbP; k += 128) {
                float v = (k < kEmbed) ? __ldg(emb + (size_t)row * kEmbed + k) : 0.f;
                __half hi, lo;
                split_f16(v, hi, lo);
                g_emb_hi[(size_t)row * kEmbP + k] = hi;
                g_emb_lo[(size_t)row * kEmbP + k] = lo;
            }
        }
    }
}

// ---------------- precompute Zpre via mma.sync (proven, unchanged) ----------------
#define PC_STG 49152
#define PC_DYN 98304

extern "C" __global__ void __launch_bounds__(256, 1) precompute_mma_kernel(
    const int* __restrict__ seq, const float* __restrict__ bias)
{
    extern __shared__ __align__(1024) char smp[];
    const uint32_t smb = smem_u32(smp);
    __shared__ int toks[128];

    const int tid = threadIdx.x;
    const int wid = tid >> 5, lane = tid & 31;
    const int nt = blockIdx.x, b = blockIdx.y;
    const int n0 = nt * 128;

    if (tid < 128) toks[tid] = seq[(size_t)b * kT + tid];
    __syncthreads();

    const int wm = (wid & 1) * 64;
    const int wn = (wid >> 1) * 32;

    float acc[4][4][4];
#pragma unroll
    for (int i = 0; i < 4; i++)
#pragma unroll
        for (int j = 0; j < 4; j++)
#pragma unroll
            for (int q = 0; q < 4; q++) acc[i][j][q] = 0.f;

    auto issue_chunk = [&](int kc, int stg) {
#pragma unroll
        for (int i = 0; i < 12; i++) {
            int idx = i * 256 + tid;
            uint32_t dst;
            const __half* src;
            if (idx < 2048) {
                int mat = idx >> 10, r = (idx >> 3) & 127, q = idx & 7;
                src = (mat ? g_emb_lo : g_emb_hi) + (size_t)toks[r] * kEmbP + kc * 64 + q * 8;
                uint32_t off = (uint32_t)(r * 128 + ((q ^ (r & 7)) * 16));
                dst = smb + stg * PC_STG + mat * 16384 + off;
            } else {
                int idxB = idx - 2048;
                int r = (idxB >> 3) & 127, q = idxB & 7;
                src = g_wt + (size_t)(n0 + r) * kEmbP + kc * 64 + q * 8;
                uint32_t off = (uint32_t)(r * 128 + ((q ^ (r & 7)) * 16));
                dst = smb + stg * PC_STG + 32768 + off;
            }
            CP_ASYNC16(dst, src);
        }
        CP_COMMIT();
    };

    issue_chunk(0, 0);

    const int la7 = lane & 7;
    const int arow_off = (lane >> 3) & 1;
    const int akseg   = (lane >> 4) & 1;
    const int brow_off = (lane >> 4) & 1;
    const int bkseg   = (lane >> 3) & 1;

    for (int kc = 0; kc < 5; kc++) {
        CP_WAIT0();
        __syncthreads();
        if (kc < 4) issue_chunk(kc + 1, (kc + 1) & 1);

        const uint32_t base = smb + (kc & 1) * PC_STG;
#pragma unroll
        for (int ks = 0; ks < 4; ks++) {
            uint32_t ahi[4][4], alo[4][4], bb[2][4];
#pragma unroll
            for (int mf = 0; mf < 4; mf++) {
                int row = wm + mf * 16 + la7 + arow_off * 8;
                uint32_t off = (uint32_t)(row * 128 + ks * 32 + akseg * 16);
                off ^= (uint32_t)((row & 7) * 16);
                LDMATRIX_X4(ahi[mf][0], ahi[mf][1], ahi[mf][2], ahi[mf][3], base + off);
                LDMATRIX_X4(alo[mf][0], alo[mf][1], alo[mf][2], alo[mf][3], base + 16384 + off);
            }
#pragma unroll
            for (int p = 0; p < 2; p++) {
                int row = wn + p * 16 + la7 + brow_off * 8;
                uint32_t off = (uint32_t)(row * 128 + ks * 32 + bkseg * 16);
                off ^= (uint32_t)((row & 7) * 16);
                LDMATRIX_X4(bb[p][0], bb[p][1], bb[p][2], bb[p][3], base + 32768 + off);
            }
#pragma unroll
            for (int mf = 0; mf < 4; mf++)
#pragma unroll
                for (int nf = 0; nf < 4; nf++) {
                    const int p = nf >> 1, s = (nf & 1) * 2;
                    float* c = acc[mf][nf];
                    MMA_F16(c[0], c[1], c[2], c[3],
                            ahi[mf][0], ahi[mf][1], ahi[mf][2], ahi[mf][3],
                            bb[p][s], bb[p][s + 1]);
                    MMA_F16(c[0], c[1], c[2], c[3],
                            alo[mf][0], alo[mf][1], alo[mf][2], alo[mf][3],
                            bb[p][s], bb[p][s + 1]);
                }
        }
    }

    __syncthreads();
    float* zs = (float*)smp;
    {
        const int cr = lane >> 2, cc = (lane & 3) * 2;
#pragma unroll
        for (int mf = 0; mf < 4; mf++)
#pragma unroll
            for (int nf = 0; nf < 4; nf++) {
                int row = wm + mf * 16 + cr;
                int col = wn + nf * 8 + cc;
                *(float2*)&zs[row * 128 + col]       = make_float2(acc[mf][nf][0], acc[mf][nf][1]);
                *(float2*)&zs[(row + 8) * 128 + col] = make_float2(acc[mf][nf][2], acc[mf][nf][3]);
            }
    }
    __syncthreads();

    const int cseg = tid & 31;
    float4 bv = __ldg((const float4*)(bias + n0 + cseg * 4));
#pragma unroll
    for (int i = 0; i < 16; i++) {
        int r = i * 8 + (tid >> 5);
        float4 v = *(const float4*)&zs[r * 128 + cseg * 4];
        v.x += bv.x; v.y += bv.y; v.z += bv.z; v.w += bv.w;
        *(float4*)(g_zpre + ((size_t)b * kT + r) * kG + n0 + cseg * 4) = v;
    }
}

// ================= shared layout for both persistent variants =================
#define RK_A_OFF 131072
#define RK_Z_OFF 196608
#define RK_DYN   229376

// ---------------- persistent LSTM, CLUSTER variant (DSMEM h-exchange) ----------------
// grid (16 nt, 8 mt), cluster (16,1,1): one cluster per mt group.
// Each CTA: U slice resident (128KB), A(h) 64KB, z 32KB. Epilogue: 1 row x 8 units
// per thread; h slice stored into ALL 16 peers' A buffers via st.shared::cluster.
extern "C" __global__ void __launch_bounds__(256, 1) lstm_cluster_kernel(
    const int* __restrict__ seq,
    const float* __restrict__ h0,
    const float* __restrict__ c0,
    float* __restrict__ out)
{
    extern __shared__ __align__(1024) char smp[];
    __shared__ __align__(8) uint64_t mbar_s;
    const uint32_t smb = smem_u32(smp);
    const uint32_t mb = smem_u32(&mbar_s);

    const int tid = threadIdx.x;
    const int wid = tid >> 5, lane = tid & 31;
    const int nt = blockIdx.x, mt = blockIdx.y;
    const int b0 = mt * 64;
    const int u0g = nt * 32;

    if (tid == 0) {
        MBAR_INIT(mb, 1);
        asm volatile("fence.proxy.async.shared::cta;" ::: "memory");
    }
    __syncthreads();
    if (tid == 0) {
        MBAR_EXPECT_TX(mb, 196608u);
        TMA_BULK(smb,            g_ur + (size_t)nt * 65536, 131072u, mb);
        TMA_BULK(smb + RK_A_OFF, g_hx[0] + (size_t)mt * 32768, 65536u, mb);
    }

    // ---- per-thread cells: 1 row x 8 units ----
    const int rb = tid >> 2;           // row 0..63
    const int uq = tid & 3;            // unit octet 0..3
    const int ub = u0g + uq * 8;       // first global unit
    const int bown = b0 + rb;
    float4 cregA, cregB, zpA[4], zpB[4];
    int seqv;
    cregA = __ldg((const float4*)(c0 + (size_t)bown * kUnits + ub));
    cregB = __ldg((const float4*)(c0 + (size_t)bown * kUnits + ub + 4));
    auto prefetch_z = [&](int t) {
        const float* zp = g_zpre + ((size_t)bown * kT + t) * kG;
#pragma unroll
        for (int g = 0; g < 4; g++) {
            zpA[g] = __ldg((const float4*)(zp + g * kUnits + ub));
            zpB[g] = __ldg((const float4*)(zp + g * kUnits + ub + 4));
        }
        seqv = __ldg(seq + (size_t)bown * kT + t);
    };
    prefetch_z(0);

    const int wm = (wid & 1) * 32;
    const int wn = (wid >> 1) * 32;
    const int la7 = lane & 7;
    const int arow_off = (lane >> 3) & 1;
    const int akseg   = (lane >> 4) & 1;
    const int brow_off = (lane >> 4) & 1;
    const int bkseg   = (lane >> 3) & 1;

    float* zs = (float*)(smp + RK_Z_OFF);
    float* hfin = out + (size_t)kB * kT * kUnits;
    float* cfin = hfin + (size_t)kB * kUnits;
    // DSMEM write target offset (same formula as A-layout): q = ub>>3 = nt*4+uq
    const int qw = nt * 4 + uq;
    const uint32_t aoff = (uint32_t)(RK_A_OFF + rb * 1024 + ((qw & 56) | ((qw ^ rb) & 7)) * 16);

    MBAR_WAIT(mb, 0);     // U + h0 resident
    __syncthreads();

    for (int t = 0; t < kT; t++) {
        float acc[2][4][4];
#pragma unroll
        for (int i = 0; i < 2; i++)
#pragma unroll
            for (int j = 0; j < 4; j++)
#pragma unroll
                for (int q = 0; q < 4; q++) acc[i][j][q] = 0.f;

        // ---- GEMM: 32 ksteps over resident smem ----
#pragma unroll 4
        for (int ks = 0; ks < 32; ks++) {
            uint32_t aa[2][4], bb[2][4];
            const int qA = ks * 2 + akseg;
            const int qB = ks * 2 + bkseg;
#pragma unroll
            for (int mf = 0; mf < 2; mf++) {
                int row = wm + mf * 16 + la7 + arow_off * 8;
                uint32_t off = (uint32_t)(row * 1024 + (((qA & 56) | ((qA ^ row) & 7)) << 4));
                LDMATRIX_X4(aa[mf][0], aa[mf][1], aa[mf][2], aa[mf][3], smb + RK_A_OFF + off);
            }
#pragma unroll
            for (int p = 0; p < 2; p++) {
                int row = wn + p * 16 + la7 + brow_off * 8;
                uint32_t off = (uint32_t)(row * 1024 + (((qB & 56) | ((qB ^ row) & 7)) << 4));
                LDMATRIX_X4(bb[p][0], bb[p][1], bb[p][2], bb[p][3], smb + off);
            }
#pragma unroll
            for (int mf = 0; mf < 2; mf++)
#pragma unroll
                for (int nf = 0; nf < 4; nf++) {
                    const int p = nf >> 1, s = (nf & 1) * 2;
                    float* c = acc[mf][nf];
                    MMA_F16(c[0], c[1], c[2], c[3],
                            aa[mf][0], aa[mf][1], aa[mf][2], aa[mf][3],
                            bb[p][s], bb[p][s + 1]);
                }
        }

        // ---- stage z ----
        __syncthreads();
        {
            const int cr = lane >> 2, cc = (lane & 3) * 2;
#pragma unroll
            for (int mf = 0; mf < 2; mf++)
#pragma unroll
                for (int nf = 0; nf < 4; nf++) {
                    int row = wm + mf * 16 + cr;
                    int col = wn + nf * 8 + cc;
                    *(float2*)&zs[row * 128 + col]       = make_float2(acc[mf][nf][0], acc[mf][nf][1]);
                    *(float2*)&zs[(row + 8) * 128 + col] = make_float2(acc[mf][nf][2], acc[mf][nf][3]);
                }
        }
        __syncthreads();

        CLUSTER_ARRIVE();   // signal: this CTA finished reading A for step t

        // ---- fused LSTM epilogue (1 row x 8 units) ----
        const bool lastt = (t == kT - 1);
        const float* hprev = (t == 0) ? h0 : (out + (size_t)(t - 1) * kUnits);
        const int hstride = (t == 0) ? kUnits : (kT * kUnits);

        float hv8[8], cv8[8];
        {
            const float* ca = (const float*)&cregA;
            const float* cb = (const float*)&cregB;
#pragma unroll
            for (int j = 0; j < 8; j++) {
                float4 zq = *(const float4*)&zs[rb * 128 + (uq * 8 + j) * 4];
                float zi = zq.x + ((const float*)&zpA[0])[0];  // placeholder, fixed below
                (void)zi;
                float zpi = (j < 4) ? ((const float*)&zpA[0])[j] : ((const float*)&zpB[0])[j - 4];
                float zpf_ = (j < 4) ? ((const float*)&zpA[1])[j] : ((const float*)&zpB[1])[j - 4];
                float zpg = (j < 4) ? ((const float*)&zpA[2])[j] : ((const float*)&zpB[2])[j - 4];
                float zpo = (j < 4) ? ((const float*)&zpA[3])[j] : ((const float*)&zpB[3])[j - 4];
                float vi = zq.x + zpi;
                float vf = zq.y + zpf_;
                float vg = zq.z + zpg;
                float vo = zq.w + zpo;
                float ig = fast_sig(vi);
                float fg = fast_sig(vf);
                float og = fast_sig(vo);
                float cold = (j < 4) ? ca[j] : cb[j - 4];
                float cnew = fmaf(fg, cold, ig * fast_tanh(vg));
                hv8[j] = og * fast_tanh(cnew);
                cv8[j] = cnew;
            }
        }
        if (seqv == 0) {
            float4 hpA = __ldg((const float4*)(hprev + (size_t)bown * hstride + ub));
            float4 hpB = __ldg((const float4*)(hprev + (size_t)bown * hstride + ub + 4));
#pragma unroll
            for (int j = 0; j < 4; j++) {
                hv8[j] = ((const float*)&hpA)[j];
                hv8[4 + j] = ((const float*)&hpB)[j];
                cv8[j] = ((const float*)&cregA)[j];
                cv8[4 + j] = ((const float*)&cregB)[j];
            }
        }
        cregA = make_float4(cv8[0], cv8[1], cv8[2], cv8[3]);
        cregB = make_float4(cv8[4], cv8[5], cv8[6], cv8[7]);
        {
            float* orow = out + (size_t)bown * (kT * kUnits) + (size_t)t * kUnits + ub;
            *(float4*)orow       = make_float4(hv8[0], hv8[1], hv8[2], hv8[3]);
            *(float4*)(orow + 4) = make_float4(hv8[4], hv8[5], hv8[6], hv8[7]);
            if (lastt) {
                *(float4*)(hfin + (size_t)bown * kUnits + ub)     = *(float4*)hv8;
                *(float4*)(hfin + (size_t)bown * kUnits + ub + 4) = *(float4*)(hv8 + 4);
                *(float4*)(cfin + (size_t)bown * kUnits + ub)     = cregA;
                *(float4*)(cfin + (size_t)bown * kUnits + ub + 4) = cregB;
            }
        }
        if (lastt) break;

        // pack 8 fp16 (16B)
        uint4 hpk;
        {
            __half2 p0 = __floats2half2_rn(hv8[0], hv8[1]);
            __half2 p1 = __floats2half2_rn(hv8[2], hv8[3]);
            __half2 p2 = __floats2half2_rn(hv8[4], hv8[5]);
            __half2 p3 = __floats2half2_rn(hv8[6], hv8[7]);
            hpk = make_uint4(*(uint32_t*)&p0, *(uint32_t*)&p1, *(uint32_t*)&p2, *(uint32_t*)&p3);
        }

        CLUSTER_WAIT();     // ALL peers finished reading A -> safe to overwrite

        // ---- DSMEM: store h slice into every peer's A buffer (incl. self) ----
#pragma unroll
        for (int j = 0; j < 16; j++) {
            uint32_t pa = mapa_rank(smb + aoff, (uint32_t)j);
            ST_CLUSTER128(pa, hpk);
        }

        prefetch_z(t + 1);

        CLUSTER_ARRIVE();   // release stores
        CLUSTER_WAIT();     // all stores visible -> next GEMM may read A
    }
}

// ---------------- persistent LSTM, FALLBACK variant (R14, proven) ----------------
extern "C" __global__ void __launch_bounds__(256, 1) lstm_persist_kernel(
    const int* __restrict__ seq,
    const float* __restrict__ h0,
    const float* __restrict__ c0,
    float* __restrict__ out)
{
    extern __shared__ __align__(1024) char smp[];
    __shared__ __align__(8) uint64_t mbar_s;
    const uint32_t smb = smem_u32(smp);
    const uint32_t mb = smem_u32(&mbar_s);

    const int tid = threadIdx.x;
    const int wid = tid >> 5, lane = tid & 31;
    const int nt = blockIdx.x, mt = blockIdx.y;
    const int b0 = mt * 64;
    const int u0g = nt * 32;

    if (tid == 0) {
        MBAR_INIT(mb, 1);
        asm volatile("fence.proxy.async.shared::cta;" ::: "memory");
    }
    __syncthreads();
    if (tid == 0) {
        MBAR_EXPECT_TX(mb, 196608u);
        TMA_BULK(smb,            g_ur + (size_t)nt * 65536, 131072u, mb);
        TMA_BULK(smb + RK_A_OFF, g_hx[0] + (size_t)mt * 32768, 65536u, mb);
    }

    const int ug = tid & 7;
    const int rg = tid >> 3;
    const int ub = u0g + ug * 4;
    float4 creg4[2], zpf4[2][4];
    int seqv[2];
#pragma unroll
    for (int it = 0; it < 2; it++) {
        int b = b0 + rg * 2 + it;
        creg4[it] = __ldg((const float4*)(c0 + (size_t)b * kUnits + ub));
    }
    auto prefetch_z = [&](int t) {
#pragma unroll
        for (int it = 0; it < 2; it++) {
            int b = b0 + rg * 2 + it;
            const float* zp = g_zpre + ((size_t)b * kT + t) * kG;
#pragma unroll
            for (int g = 0; g < 4; g++)
                zpf4[it][g] = __ldg((const float4*)(zp + g * kUnits + ub));
            seqv[it] = __ldg(seq + (size_t)b * kT + t);
        }
    };
    prefetch_z(0);

    const int wm = (wid & 1) * 32;
    const int wn = (wid >> 1) * 32;
    const int la7 = lane & 7;
    const int arow_off = (lane >> 3) & 1;
    const int akseg   = (lane >> 4) & 1;
    const int brow_off = (lane >> 4) & 1;
    const int bkseg   = (lane >> 3) & 1;

    float* zs = (float*)(smp + RK_Z_OFF);
    float* hfin = out + (size_t)kB * kT * kUnits;
    float* cfin = hfin + (size_t)kB * kUnits;
    const int qw = (ub >> 3);
    const int lnw = ub & 7;

    for (int t = 0; t < kT; t++) {
        MBAR_WAIT(mb, t & 1);

        float acc[2][4][4];
#pragma unroll
        for (int i = 0; i < 2; i++)
#pragma unroll
            for (int j = 0; j < 4; j++)
#pragma unroll
                for (int q = 0; q < 4; q++) acc[i][j][q] = 0.f;

#pragma unroll 4
        for (int ks = 0; ks < 32; ks++) {
            uint32_t aa[2][4], bb[2][4];
            const int qA = ks * 2 + akseg;
            const int qB = ks * 2 + bkseg;
#pragma unroll
            for (int mf = 0; mf < 2; mf++) {
                int row = wm + mf * 16 + la7 + arow_off * 8;
                uint32_t off = (uint32_t)(row * 1024 + (((qA & 56) | ((qA ^ row) & 7)) << 4));
                LDMATRIX_X4(aa[mf][0], aa[mf][1], aa[mf][2], aa[mf][3], smb + RK_A_OFF + off);
            }
#pragma unroll
            for (int p = 0; p < 2; p++) {
                int row = wn + p * 16 + la7 + brow_off * 8;
                uint32_t off = (uint32_t)(row * 1024 + (((qB & 56) | ((qB ^ row) & 7)) << 4));
                LDMATRIX_X4(bb[p][0], bb[p][1], bb[p][2], bb[p][3], smb + off);
            }
#pragma unroll
            for (int mf = 0; mf < 2; mf++)
#pragma unroll
                for (int nf = 0; nf < 4; nf++) {
                    const int p = nf >> 1, s = (nf & 1) * 2;
                    float* c = acc[mf][nf];
                    MMA_F16(c[0], c[1], c[2], c[3],
                            aa[mf][0], aa[mf][1], aa[mf][2], aa[mf][3],
                            bb[p][s], bb[p][s + 1]);
                }
        }

        __syncthreads();
        {
            const int cr = lane >> 2, cc = (lane & 3) * 2;
#pragma unroll
            for (int mf = 0; mf < 2; mf++)
#pragma unroll
                for (int nf = 0; nf < 4; nf++) {
                    int row = wm + mf * 16 + cr;
                    int col = wn + nf * 8 + cc;
                    *(float2*)&zs[row * 128 + col]       = make_float2(acc[mf][nf][0], acc[mf][nf][1]);
                    *(float2*)&zs[(row + 8) * 128 + col] = make_float2(acc[mf][nf][2], acc[mf][nf][3]);
                }
        }
        __syncthreads();

        __half* hx = g_hx[(t + 1) & 1] + (size_t)mt * 32768;
        const bool lastt = (t == kT - 1);
        const float* hprev = (t == 0) ? h0 : (out + (size_t)(t - 1) * kUnits);
        const int hstride = (t == 0) ? kUnits : (kT * kUnits);
#pragma unroll
        for (int it = 0; it < 2; it++) {
            int rb = rg * 2 + it;
            int b = b0 + rb;
            float4 zq[4];
#pragma unroll
            for (int j = 0; j < 4; j++)
                zq[j] = *(const float4*)&zs[rb * 128 + ug * 16 + j * 4];

            float4 hv, cv;
            float* hp = (float*)&hv;
            float* cp = (float*)&cv;
            const float* cold4 = (const float*)&creg4[it];
#pragma unroll
            for (int j = 0; j < 4; j++) {
                float zi = zq[j].x + ((const float*)&zpf4[it][0])[j];
                float zf = zq[j].y + ((const float*)&zpf4[it][1])[j];
                float zg = zq[j].z + ((const float*)&zpf4[it][2])[j];
                float zo = zq[j].w + ((const float*)&zpf4[it][3])[j];
                float ig = fast_sig(zi);
                float fg = fast_sig(zf);
                float og = fast_sig(zo);
                float cnew = fmaf(fg, cold4[j], ig * fast_tanh(zg));
                hp[j] = og * fast_tanh(cnew);
                cp[j] = cnew;
            }
            if (seqv[it] == 0) {
                cv = creg4[it];
                hv = __ldg((const float4*)(hprev + (size_t)b * hstride + ub));
            }
            creg4[it] = cv;
            *(float4*)(out + (size_t)b * (kT * kUnits) + (size_t)t * kUnits + ub) = hv;
            __half2 h01 = __floats2half2_rn(hv.x, hv.y);
            __half2 h23 = __floats2half2_rn(hv.z, hv.w);
            uint2 hpk = make_uint2(*(uint32_t*)&h01, *(uint32_t*)&h23);
            *(uint2*)(hx + rb * 512 + ((qw & 56) | ((qw ^ rb) & 7)) * 8 + lnw) = hpk;
            if (lastt) {
                *(float4*)(hfin + (size_t)b * kUnits + ub) = hv;
                *(float4*)(cfin + (size_t)b * kUnits + ub) = cv;
            }
        }
        if (t == kT - 1) break;

        prefetch_z(t + 1);

        __threadfence();
        __syncthreads();
        if (tid == 0) {
            asm volatile("red.release.gpu.global.add.u32 [%0], 1;"
                         :: "l"(&g_bar[mt]) : "memory");
            unsigned target = 16u * (unsigned)(t + 1);
            unsigned v;
            do {
                asm volatile("ld.acquire.gpu.global.u32 %0, [%1];"
                             : "=r"(v) : "l"(&g_bar[mt]) : "memory");
                if (v < target) __nanosleep(32);
            } while (v < target);
        }
        __syncthreads();
        if (tid == 0) {
            MBAR_EXPECT_TX(mb, 65536u);
            TMA_BULK(smb + RK_A_OFF, g_hx[(t + 1) & 1] + (size_t)mt * 32768, 65536u, mb);
        }
    }
}

// ---------------- host ----------------
extern "C" void kernel_launch(void* const* d_in, const int* in_sizes, int n_in,
                              void* d_out, int out_size)
{
    const int*   seq  = (const int*)d_in[0];
    const float* h0   = (const float*)d_in[1];
    const float* c0   = (const float*)d_in[2];
    const float* emb  = (const float*)d_in[3];
    const float* W    = (const float*)d_in[4];
    const float* Umat = (const float*)d_in[5];
    const float* bias = (const float*)d_in[6];
    float* out = (float*)d_out;

    static int mode = -1;    // -1 unknown, 1 cluster, 0 fallback
    if (mode == -1) {
        cudaFuncSetAttribute(precompute_mma_kernel, cudaFuncAttributeMaxDynamicSharedMemorySize, PC_DYN);
        cudaFuncSetAttribute(lstm_persist_kernel, cudaFuncAttributeMaxDynamicSharedMemorySize, RK_DYN);
        cudaFuncSetAttribute(lstm_cluster_kernel, cudaFuncAttributeMaxDynamicSharedMemorySize, RK_DYN);
        cudaFuncSetAttribute(lstm_cluster_kernel, cudaFuncAttributeNonPortableClusterSizeAllowed, 1);
    }

    const int embBlocks = (kVocab + 7) / 8;
    prep_kernel<<<kG + 8 + kG + embBlocks, 128>>>(Umat, h0, W, emb);

    precompute_mma_kernel<<<dim3(16, kB), 256, PC_DYN>>>(seq, bias);

    bool launched = false;
    if (mode != 0) {
        cudaLaunchConfig_t cfg = {};
        cfg.gridDim = dim3(16, 8, 1);
        cfg.blockDim = dim3(256, 1, 1);
        cfg.dynamicSmemBytes = RK_DYN;
        cudaLaunchAttribute attrs[1];
        attrs[0].id = cudaLaunchAttributeClusterDimension;
        attrs[0].val.clusterDim = {16, 1, 1};
        cfg.attrs = attrs;
        cfg.numAttrs = 1;
        cudaError_t rc = cudaLaunchKernelEx(&cfg, lstm_cluster_kernel, seq, h0, c0, out);
        if (rc == cudaSuccess) {
            mode = 1;
            launched = true;
        } else {
            cudaGetLastError();   // clear
            mode = 0;
        }
    }
    if (!launched)
        lstm_persist_kernel<<<dim3(16, 8), 256, RK_DYN>>>(seq, h0, c0, out);
}

// round 16
// speedup vs baseline: 1.6271x; 1.6271x over previous
#include <cuda_runtime.h>
#include <cuda_fp16.h>
#include <cstdint>
#include <math.h>

#define kVocab 50000
#define kEmbed 300
#define kEmbP  320
#define kUnits 512
#define kT 128
#define kB 512
#define kG 2048

// ---------------- global scratch ----------------
__device__ __half g_zpre_h[(size_t)kB * kT * kG];                // pre-activations fp16 (256MB)
__device__ float g_c[(size_t)kB * kUnits];
__device__ __align__(128) __half g_u[kG * kUnits];               // U^T gate-interleaved, fp16
__device__ __align__(128) __half g_hb[2][kB * kUnits];           // h fp16, double buffered [b][k]
__device__ __align__(128) __half g_emb_hi[(size_t)kVocab * kEmbP];
__device__ __align__(128) __half g_emb_lo[(size_t)kVocab * kEmbP];
__device__ __align__(128) __half g_wt[kG * kEmbP];

// ---------------- helpers ----------------
__device__ __forceinline__ uint32_t smem_u32(const void* p) {
    uint32_t a;
    asm("{ .reg .u64 t; cvta.to.shared.u64 t, %1; cvt.u32.u64 %0, t; }" : "=r"(a) : "l"(p));
    return a;
}
#define CP_ASYNC16(dst, src) \
    asm volatile("cp.async.cg.shared.global [%0], [%1], 16;" :: "r"(dst), "l"(src) : "memory")
#define CP_COMMIT() asm volatile("cp.async.commit_group;" ::: "memory")
#define CP_WAIT0()  asm volatile("cp.async.wait_group 0;" ::: "memory")
#define CP_WAIT1()  asm volatile("cp.async.wait_group 1;" ::: "memory")

#define LDMATRIX_X4(r0, r1, r2, r3, addr) \
    asm volatile("ldmatrix.sync.aligned.m8n8.x4.shared.b16 {%0,%1,%2,%3}, [%4];" \
        : "=r"(r0), "=r"(r1), "=r"(r2), "=r"(r3) : "r"(addr))

#define MMA_F16(c0, c1, c2, c3, a0, a1, a2, a3, b0, b1) \
    asm volatile("mma.sync.aligned.m16n8k16.row.col.f32.f16.f16.f32 " \
        "{%0,%1,%2,%3}, {%4,%5,%6,%7}, {%8,%9}, {%0,%1,%2,%3};" \
        : "+f"(c0), "+f"(c1), "+f"(c2), "+f"(c3) \
        : "r"(a0), "r"(a1), "r"(a2), "r"(a3), "r"(b0), "r"(b1))

__device__ __forceinline__ float fast_ex2(float x) { float y; asm("ex2.approx.ftz.f32 %0, %1;" : "=f"(y) : "f"(x)); return y; }
__device__ __forceinline__ float fast_sig(float x) { return __fdividef(1.f, 1.f + fast_ex2(-1.4426950408889634f * x)); }
__device__ __forceinline__ float fast_tanh(float x) {
    float ax = fabsf(x);
    float e = fast_ex2(-2.8853900817779268f * ax);
    float t = __fdividef(1.f - e, 1.f + e);
    return copysignf(t, x);
}
__device__ __forceinline__ void split_f16(float v, __half& hi, __half& lo) {
    hi = __float2half_rn(v);
    lo = __float2half_rn(v - __half2float(hi));
}

// ---------------- prep (vectorized stores) ----------------
__global__ __launch_bounds__(128) void prep_kernel(const float* __restrict__ U,
                                                   const float* __restrict__ h0,
                                                   const float* __restrict__ W,
                                                   const float* __restrict__ emb) {
    int blk = blockIdx.x;
    if (blk < kG) {                       // U^T gate-interleaved n'=u*4+g, 16B stores
        int np = blk;
        int n = (np & 3) * kUnits + (np >> 2);
        for (int q = threadIdx.x; q < 64; q += 128) {
            __half tmp[8];
#pragma unroll
            for (int ln = 0; ln < 8; ln++)
                tmp[ln] = __float2half_rn(__ldg(U + (size_t)(q * 8 + ln) * kG + n));
            *(uint4*)&g_u[np * kUnits + q * 8] = *(uint4*)tmp;
        }
    } else if (blk < kG + 8) {            // h0 -> fp16 into buffer 1, 16B stores
        int r0 = (blk - kG) * 64;
        for (int i = threadIdx.x; i < 4096; i += 128) {
            int r = r0 + (i >> 6), q = i & 63;
            float4 a = __ldg((const float4*)(h0 + (size_t)r * kUnits + q * 8));
            float4 b = __ldg((const float4*)(h0 + (size_t)r * kUnits + q * 8 + 4));
            __half tmp[8] = { __float2half_rn(a.x), __float2half_rn(a.y),
                              __float2half_rn(a.z), __float2half_rn(a.w),
                              __float2half_rn(b.x), __float2half_rn(b.y),
                              __float2half_rn(b.z), __float2half_rn(b.w) };
            *(uint4*)&g_hb[1][r * kUnits + q * 8] = *(uint4*)tmp;
        }
    } else if (blk < kG + 8 + kG) {       // W^T row n, padded K
        int n = blk - kG - 8;
        for (int k = threadIdx.x; k < kEmbP; k += 128) {
            float v = (k < kEmbed) ? __ldg(W + (size_t)k * kG + n) : 0.f;
            g_wt[n * kEmbP + k] = __float2half_rn(v);
        }
    } else {                              // emb rows, padded, fp16 hi/lo
        int r0 = (blk - kG - 8 - kG) * 8;
        for (int rr = 0; rr < 8; rr++) {
            int row = r0 + rr;
            if (row >= kVocab) break;
            for (int k = threadIdx.x; k < kEmbP; k += 128) {
                float v = (k < kEmbed) ? __ldg(emb + (size_t)row * kEmbed + k) : 0.f;
                __half hi, lo;
                split_f16(v, hi, lo);
                g_emb_hi[(size_t)row * kEmbP + k] = hi;
                g_emb_lo[(size_t)row * kEmbP + k] = lo;
            }
        }
    }
}

// ---------------- precompute Zpre via mma.sync, fp16 output ----------------
#define PC_STG 49152
#define PC_DYN 98304

extern "C" __global__ void __launch_bounds__(256, 1) precompute_mma_kernel(
    const int* __restrict__ seq, const float* __restrict__ bias)
{
    extern __shared__ __align__(1024) char smp[];
    const uint32_t smb = smem_u32(smp);
    __shared__ int toks[128];

    const int tid = threadIdx.x;
    const int wid = tid >> 5, lane = tid & 31;
    const int nt = blockIdx.x, b = blockIdx.y;
    const int n0 = nt * 128;

    if (tid < 128) toks[tid] = seq[(size_t)b * kT + tid];
    __syncthreads();

    const int wm = (wid & 1) * 64;
    const int wn = (wid >> 1) * 32;

    float acc[4][4][4];
#pragma unroll
    for (int i = 0; i < 4; i++)
#pragma unroll
        for (int j = 0; j < 4; j++)
#pragma unroll
            for (int q = 0; q < 4; q++) acc[i][j][q] = 0.f;

    auto issue_chunk = [&](int kc, int stg) {
#pragma unroll
        for (int i = 0; i < 12; i++) {
            int idx = i * 256 + tid;
            uint32_t dst;
            const __half* src;
            if (idx < 2048) {
                int mat = idx >> 10, r = (idx >> 3) & 127, q = idx & 7;
                src = (mat ? g_emb_lo : g_emb_hi) + (size_t)toks[r] * kEmbP + kc * 64 + q * 8;
                uint32_t off = (uint32_t)(r * 128 + ((q ^ (r & 7)) * 16));
                dst = smb + stg * PC_STG + mat * 16384 + off;
            } else {
                int idxB = idx - 2048;
                int r = (idxB >> 3) & 127, q = idxB & 7;
                src = g_wt + (size_t)(n0 + r) * kEmbP + kc * 64 + q * 8;
                uint32_t off = (uint32_t)(r * 128 + ((q ^ (r & 7)) * 16));
                dst = smb + stg * PC_STG + 32768 + off;
            }
            CP_ASYNC16(dst, src);
        }
        CP_COMMIT();
    };

    issue_chunk(0, 0);

    const int la7 = lane & 7;
    const int arow_off = (lane >> 3) & 1;
    const int akseg   = (lane >> 4) & 1;
    const int brow_off = (lane >> 4) & 1;
    const int bkseg   = (lane >> 3) & 1;

    for (int kc = 0; kc < 5; kc++) {
        CP_WAIT0();
        __syncthreads();
        if (kc < 4) issue_chunk(kc + 1, (kc + 1) & 1);

        const uint32_t base = smb + (kc & 1) * PC_STG;
#pragma unroll
        for (int ks = 0; ks < 4; ks++) {
            uint32_t ahi[4][4], alo[4][4], bb[2][4];
#pragma unroll
            for (int mf = 0; mf < 4; mf++) {
                int row = wm + mf * 16 + la7 + arow_off * 8;
                uint32_t off = (uint32_t)(row * 128 + ks * 32 + akseg * 16);
                off ^= (uint32_t)((row & 7) * 16);
                LDMATRIX_X4(ahi[mf][0], ahi[mf][1], ahi[mf][2], ahi[mf][3], base + off);
                LDMATRIX_X4(alo[mf][0], alo[mf][1], alo[mf][2], alo[mf][3], base + 16384 + off);
            }
#pragma unroll
            for (int p = 0; p < 2; p++) {
                int row = wn + p * 16 + la7 + brow_off * 8;
                uint32_t off = (uint32_t)(row * 128 + ks * 32 + bkseg * 16);
                off ^= (uint32_t)((row & 7) * 16);
                LDMATRIX_X4(bb[p][0], bb[p][1], bb[p][2], bb[p][3], base + 32768 + off);
            }
#pragma unroll
            for (int mf = 0; mf < 4; mf++)
#pragma unroll
                for (int nf = 0; nf < 4; nf++) {
                    const int p = nf >> 1, s = (nf & 1) * 2;
                    float* c = acc[mf][nf];
                    MMA_F16(c[0], c[1], c[2], c[3],
                            ahi[mf][0], ahi[mf][1], ahi[mf][2], ahi[mf][3],
                            bb[p][s], bb[p][s + 1]);
                    MMA_F16(c[0], c[1], c[2], c[3],
                            alo[mf][0], alo[mf][1], alo[mf][2], alo[mf][3],
                            bb[p][s], bb[p][s + 1]);
                }
        }
    }

    __syncthreads();
    float* zs = (float*)smp;
    {
        const int cr = lane >> 2, cc = (lane & 3) * 2;
#pragma unroll
        for (int mf = 0; mf < 4; mf++)
#pragma unroll
            for (int nf = 0; nf < 4; nf++) {
                int row = wm + mf * 16 + cr;
                int col = wn + nf * 8 + cc;
                *(float2*)&zs[row * 128 + col]       = make_float2(acc[mf][nf][0], acc[mf][nf][1]);
                *(float2*)&zs[(row + 8) * 128 + col] = make_float2(acc[mf][nf][2], acc[mf][nf][3]);
            }
    }
    __syncthreads();

    const int cseg = tid & 31;
    float4 bv = __ldg((const float4*)(bias + n0 + cseg * 4));
#pragma unroll
    for (int i = 0; i < 16; i++) {
        int r = i * 8 + (tid >> 5);
        float4 v = *(const float4*)&zs[r * 128 + cseg * 4];
        __half2 p0 = __floats2half2_rn(v.x + bv.x, v.y + bv.y);
        __half2 p1 = __floats2half2_rn(v.z + bv.z, v.w + bv.w);
        uint2 pk = make_uint2(*(uint32_t*)&p0, *(uint32_t*)&p1);
        *(uint2*)(g_zpre_h + ((size_t)b * kT + r) * kG + n0 + cseg * 4) = pk;
    }
}

// ---------------- mma.sync LSTM step (R11 GEMM + vectorized fp16-z epilogue) ----------------
// grid (16 nt, 8 mt) = 128 CTAs, 256 thr (8 warps 2x4), warp tile 32x32.
// CTA tile M=64 x N=128, K=512 in 8 chunks of 64. stage 24KB x 3 = 72KB.
// Cell map: 2 rows x 4 consecutive units per thread (all epilogue LSU vectorized).
#define ST_STG 24576
#define ST_DYN 73728

extern "C" __global__ void __launch_bounds__(256, 1) step_mma_kernel(
    int t,
    const int* __restrict__ seq,
    const float* __restrict__ hprev_f32, int hstride,
    const float* __restrict__ c0,
    float* __restrict__ out)
{
    extern __shared__ __align__(1024) char smp[];
    const uint32_t smb = smem_u32(smp);

    const int tid = threadIdx.x;
    const int wid = tid >> 5, lane = tid & 31;
    const int nt = blockIdx.x, mt = blockIdx.y;
    const int b0 = mt * 64;
    const int n0 = nt * 128;
    const int u0g = nt * 32;

    // ---- epilogue operand prefetch: 2 rows x 4 units per thread ----
    const int ug = tid & 7;            // unit quad 0..7
    const int rg = tid >> 3;           // row pair 0..31
    const int ub = u0g + ug * 4;
    float4 creg4[2], zpf4[2][4];
    int seqv[2];
    {
        const float* cin = (t == 0) ? c0 : g_c;
#pragma unroll
        for (int it = 0; it < 2; it++) {
            int b = b0 + rg * 2 + it;
            creg4[it] = __ldg((const float4*)(cin + (size_t)b * kUnits + ub));
            const __half* zp = g_zpre_h + ((size_t)b * kT + t) * kG;
#pragma unroll
            for (int g = 0; g < 4; g++) {
                uint2 raw = __ldg((const uint2*)(zp + g * kUnits + ub));
                __half2 h0v = *(__half2*)&raw.x;
                __half2 h1v = *(__half2*)&raw.y;
                zpf4[it][g] = make_float4(__low2float(h0v), __high2float(h0v),
                                          __low2float(h1v), __high2float(h1v));
            }
            seqv[it] = __ldg(seq + (size_t)b * kT + t);
        }
    }

    const __half* srcA = g_hb[(t + 1) & 1] + (size_t)b0 * kUnits;
    const __half* srcB = g_u + (size_t)n0 * kUnits;

    const int wm = (wid & 1) * 32;
    const int wn = (wid >> 1) * 32;

    float acc[2][4][4];
#pragma unroll
    for (int i = 0; i < 2; i++)
#pragma unroll
        for (int j = 0; j < 4; j++)
#pragma unroll
            for (int q = 0; q < 4; q++) acc[i][j][q] = 0.f;

    auto issue_chunk = [&](int kc, int stg) {
#pragma unroll
        for (int i = 0; i < 6; i++) {
            int idx = i * 256 + tid;       // 0..1535
            uint32_t dst;
            const __half* src;
            if (idx < 512) {               // A: h rows (64)
                int r = idx >> 3, q = idx & 7;
                src = srcA + (size_t)r * kUnits + kc * 64 + q * 8;
                uint32_t off = (uint32_t)(r * 128 + ((q ^ (r & 7)) * 16));
                dst = smb + stg * ST_STG + off;
            } else {                       // B: U rows (128)
                int idxB = idx - 512;
                int r = idxB >> 3, q = idxB & 7;
                src = srcB + (size_t)r * kUnits + kc * 64 + q * 8;
                uint32_t off = (uint32_t)(r * 128 + ((q ^ (r & 7)) * 16));
                dst = smb + stg * ST_STG + 8192 + off;
            }
            CP_ASYNC16(dst, src);
        }
        CP_COMMIT();
    };

    issue_chunk(0, 0);
    issue_chunk(1, 1);

    const int la7 = lane & 7;
    const int arow_off = (lane >> 3) & 1;
    const int akseg   = (lane >> 4) & 1;
    const int brow_off = (lane >> 4) & 1;
    const int bkseg   = (lane >> 3) & 1;

    for (int kc = 0; kc < 8; kc++) {
        if (kc < 6) { CP_WAIT1(); } else { CP_WAIT0(); }
        __syncthreads();
        if (kc < 6) issue_chunk(kc + 2, (kc + 2) % 3);

        const uint32_t base = smb + (kc % 3) * ST_STG;
#pragma unroll
        for (int ks = 0; ks < 4; ks++) {
            uint32_t aa[2][4], bb[2][4];
#pragma unroll
            for (int mf = 0; mf < 2; mf++) {
                int row = wm + mf * 16 + la7 + arow_off * 8;
                uint32_t off = (uint32_t)(row * 128 + ks * 32 + akseg * 16);
                off ^= (uint32_t)((row & 7) * 16);
                LDMATRIX_X4(aa[mf][0], aa[mf][1], aa[mf][2], aa[mf][3], base + off);
            }
#pragma unroll
            for (int p = 0; p < 2; p++) {
                int row = wn + p * 16 + la7 + brow_off * 8;
                uint32_t off = (uint32_t)(row * 128 + ks * 32 + bkseg * 16);
                off ^= (uint32_t)((row & 7) * 16);
                LDMATRIX_X4(bb[p][0], bb[p][1], bb[p][2], bb[p][3], base + 8192 + off);
            }
#pragma unroll
            for (int mf = 0; mf < 2; mf++)
#pragma unroll
                for (int nf = 0; nf < 4; nf++) {
                    const int p = nf >> 1, s = (nf & 1) * 2;
                    float* c = acc[mf][nf];
                    MMA_F16(c[0], c[1], c[2], c[3],
                            aa[mf][0], aa[mf][1], aa[mf][2], aa[mf][3],
                            bb[p][s], bb[p][s + 1]);
                }
        }
    }

    // ---- stage z to smem: 64x128 f32 = 32KB ----
    __syncthreads();
    float* zs = (float*)smp;
    {
        const int cr = lane >> 2, cc = (lane & 3) * 2;
#pragma unroll
        for (int mf = 0; mf < 2; mf++)
#pragma unroll
            for (int nf = 0; nf < 4; nf++) {
                int row = wm + mf * 16 + cr;
                int col = wn + nf * 8 + cc;
                *(float2*)&zs[row * 128 + col]       = make_float2(acc[mf][nf][0], acc[mf][nf][1]);
                *(float2*)&zs[(row + 8) * 128 + col] = make_float2(acc[mf][nf][2], acc[mf][nf][3]);
            }
    }
    __syncthreads();

    // ---- fused LSTM epilogue (vectorized, + finalize at t = T-1) ----
    __half* dsth = g_hb[t & 1];
    const bool lastt = (t == kT - 1);
    float* hfin = out + (size_t)kB * kT * kUnits;
    float* cfin = hfin + (size_t)kB * kUnits;
#pragma unroll
    for (int it = 0; it < 2; it++) {
        int rb = rg * 2 + it;
        int b = b0 + rb;
        float4 zq[4];
#pragma unroll
        for (int j = 0; j < 4; j++)
            zq[j] = *(const float4*)&zs[rb * 128 + ug * 16 + j * 4];

        float4 hv, cv;
        float* hp = (float*)&hv;
        float* cp = (float*)&cv;
        const float* cold4 = (const float*)&creg4[it];
#pragma unroll
        for (int j = 0; j < 4; j++) {
            float zi = zq[j].x + ((const float*)&zpf4[it][0])[j];
            float zf = zq[j].y + ((const float*)&zpf4[it][1])[j];
            float zg = zq[j].z + ((const float*)&zpf4[it][2])[j];
            float zo = zq[j].w + ((const float*)&zpf4[it][3])[j];
            float ig = fast_sig(zi);
            float fg = fast_sig(zf);
            float og = fast_sig(zo);
            float cnew = fmaf(fg, cold4[j], ig * fast_tanh(zg));
            hp[j] = og * fast_tanh(cnew);
            cp[j] = cnew;
        }
        if (seqv[it] == 0) {
            cv = creg4[it];
            hv = __ldg((const float4*)(hprev_f32 + (size_t)b * hstride + ub));
        }
        *(float4*)(g_c + (size_t)b * kUnits + ub) = cv;
        *(float4*)(out + (size_t)b * (kT * kUnits) + (size_t)t * kUnits + ub) = hv;
        __half2 h01 = __floats2half2_rn(hv.x, hv.y);
        __half2 h23 = __floats2half2_rn(hv.z, hv.w);
        uint2 hpk = make_uint2(*(uint32_t*)&h01, *(uint32_t*)&h23);
        *(uint2*)(dsth + (size_t)b * kUnits + ub) = hpk;
        if (lastt) {
            *(float4*)(hfin + (size_t)b * kUnits + ub) = hv;
            *(float4*)(cfin + (size_t)b * kUnits + ub) = cv;
        }
    }
}

// ---------------- host ----------------
extern "C" void kernel_launch(void* const* d_in, const int* in_sizes, int n_in,
                              void* d_out, int out_size)
{
    const int*   seq  = (const int*)d_in[0];
    const float* h0   = (const float*)d_in[1];
    const float* c0   = (const float*)d_in[2];
    const float* emb  = (const float*)d_in[3];
    const float* W    = (const float*)d_in[4];
    const float* Umat = (const float*)d_in[5];
    const float* bias = (const float*)d_in[6];
    float* out = (float*)d_out;

    static int configured = 0;
    if (!configured) {
        cudaFuncSetAttribute(precompute_mma_kernel, cudaFuncAttributeMaxDynamicSharedMemorySize, PC_DYN);
        cudaFuncSetAttribute(step_mma_kernel, cudaFuncAttributeMaxDynamicSharedMemorySize, ST_DYN);
        configured = 1;
    }

    const int embBlocks = (kVocab + 7) / 8;
    prep_kernel<<<kG + 8 + kG + embBlocks, 128>>>(Umat, h0, W, emb);

    precompute_mma_kernel<<<dim3(16, kB), 256, PC_DYN>>>(seq, bias);

    for (int t = 0; t < kT; t++) {
        const float* hprev = t ? (out + (size_t)(t - 1) * kUnits) : h0;
        int hstride = t ? (kT * kUnits) : kUnits;
        step_mma_kernel<<<dim3(16, 8), 256, ST_DYN>>>(t, seq, hprev, hstride, c0, out);
    }
}

// round 17
// speedup vs baseline: 1.6683x; 1.0253x over previous
#include <cuda_runtime.h>
#include <cuda_fp16.h>
#include <cstdint>
#include <math.h>

#define kVocab 50000
#define kEmbed 300
#define kEmbP  320
#define kUnits 512
#define kT 128
#define kB 512
#define kG 2048

// ---------------- global scratch ----------------
__device__ __half g_zpre_h[(size_t)kB * kT * kG];                // pre-activations fp16
__device__ float g_c[(size_t)kB * kUnits];
__device__ __align__(128) __half g_u[kG * kUnits];               // U^T gate-interleaved, fp16
__device__ __align__(128) __half g_hb[2][kB * kUnits];           // h fp16, double buffered [b][k]
__device__ __align__(128) __half g_emb_hi[(size_t)kVocab * kEmbP];
__device__ __align__(128) __half g_emb_lo[(size_t)kVocab * kEmbP];
__device__ __align__(128) __half g_wt[kG * kEmbP];

// ---------------- helpers ----------------
__device__ __forceinline__ uint32_t smem_u32(const void* p) {
    uint32_t a;
    asm("{ .reg .u64 t; cvta.to.shared.u64 t, %1; cvt.u32.u64 %0, t; }" : "=r"(a) : "l"(p));
    return a;
}
#define CP_ASYNC16(dst, src) \
    asm volatile("cp.async.cg.shared.global [%0], [%1], 16;" :: "r"(dst), "l"(src) : "memory")
#define CP_COMMIT() asm volatile("cp.async.commit_group;" ::: "memory")
#define CP_WAIT0()  asm volatile("cp.async.wait_group 0;" ::: "memory")
#define CP_WAIT1()  asm volatile("cp.async.wait_group 1;" ::: "memory")

#define GRIDDEP_WAIT()   asm volatile("griddepcontrol.wait;" ::: "memory")
#define GRIDDEP_LAUNCH() asm volatile("griddepcontrol.launch_dependents;" ::: "memory")

#define LDMATRIX_X4(r0, r1, r2, r3, addr) \
    asm volatile("ldmatrix.sync.aligned.m8n8.x4.shared.b16 {%0,%1,%2,%3}, [%4];" \
        : "=r"(r0), "=r"(r1), "=r"(r2), "=r"(r3) : "r"(addr))

#define MMA_F16(c0, c1, c2, c3, a0, a1, a2, a3, b0, b1) \
    asm volatile("mma.sync.aligned.m16n8k16.row.col.f32.f16.f16.f32 " \
        "{%0,%1,%2,%3}, {%4,%5,%6,%7}, {%8,%9}, {%0,%1,%2,%3};" \
        : "+f"(c0), "+f"(c1), "+f"(c2), "+f"(c3) \
        : "r"(a0), "r"(a1), "r"(a2), "r"(a3), "r"(b0), "r"(b1))

__device__ __forceinline__ float fast_ex2(float x) { float y; asm("ex2.approx.ftz.f32 %0, %1;" : "=f"(y) : "f"(x)); return y; }
__device__ __forceinline__ float fast_sig(float x) { return __fdividef(1.f, 1.f + fast_ex2(-1.4426950408889634f * x)); }
__device__ __forceinline__ float fast_tanh(float x) {
    float ax = fabsf(x);
    float e = fast_ex2(-2.8853900817779268f * ax);
    float t = __fdividef(1.f - e, 1.f + e);
    return copysignf(t, x);
}
__device__ __forceinline__ void split_f16(float v, __half& hi, __half& lo) {
    hi = __float2half_rn(v);
    lo = __float2half_rn(v - __half2float(hi));
}

// ---------------- prep (R16, proven) ----------------
__global__ __launch_bounds__(128) void prep_kernel(const float* __restrict__ U,
                                                   const float* __restrict__ h0,
                                                   const float* __restrict__ W,
                                                   const float* __restrict__ emb) {
    int blk = blockIdx.x;
    if (blk < kG) {
        int np = blk;
        int n = (np & 3) * kUnits + (np >> 2);
        for (int q = threadIdx.x; q < 64; q += 128) {
            __half tmp[8];
#pragma unroll
            for (int ln = 0; ln < 8; ln++)
                tmp[ln] = __float2half_rn(__ldg(U + (size_t)(q * 8 + ln) * kG + n));
            *(uint4*)&g_u[np * kUnits + q * 8] = *(uint4*)tmp;
        }
    } else if (blk < kG + 8) {
        int r0 = (blk - kG) * 64;
        for (int i = threadIdx.x; i < 4096; i += 128) {
            int r = r0 + (i >> 6), q = i & 63;
            float4 a = __ldg((const float4*)(h0 + (size_t)r * kUnits + q * 8));
            float4 b = __ldg((const float4*)(h0 + (size_t)r * kUnits + q * 8 + 4));
            __half tmp[8] = { __float2half_rn(a.x), __float2half_rn(a.y),
                              __float2half_rn(a.z), __float2half_rn(a.w),
                              __float2half_rn(b.x), __float2half_rn(b.y),
                              __float2half_rn(b.z), __float2half_rn(b.w) };
            *(uint4*)&g_hb[1][r * kUnits + q * 8] = *(uint4*)tmp;
        }
    } else if (blk < kG + 8 + kG) {
        int n = blk - kG - 8;
        for (int k = threadIdx.x; k < kEmbP; k += 128) {
            float v = (k < kEmbed) ? __ldg(W + (size_t)k * kG + n) : 0.f;
            g_wt[n * kEmbP + k] = __float2half_rn(v);
        }
    } else {
        int r0 = (blk - kG - 8 - kG) * 8;
        for (int rr = 0; rr < 8; rr++) {
            int row = r0 + rr;
            if (row >= kVocab) break;
            for (int k = threadIdx.x; k < kEmbP; k += 128) {
                float v = (k < kEmbed) ? __ldg(emb + (size_t)row * kEmbed + k) : 0.f;
                __half hi, lo;
                split_f16(v, hi, lo);
                g_emb_hi[(size_t)row * kEmbP + k] = hi;
                g_emb_lo[(size_t)row * kEmbP + k] = lo;
            }
        }
    }
}

// ---------------- precompute Zpre via mma.sync, fp16 output (R16, proven) ----------------
#define PC_STG 49152
#define PC_DYN 98304

extern "C" __global__ void __launch_bounds__(256, 1) precompute_mma_kernel(
    const int* __restrict__ seq, const float* __restrict__ bias)
{
    extern __shared__ __align__(1024) char smp[];
    const uint32_t smb = smem_u32(smp);
    __shared__ int toks[128];

    const int tid = threadIdx.x;
    const int wid = tid >> 5, lane = tid & 31;
    const int nt = blockIdx.x, b = blockIdx.y;
    const int n0 = nt * 128;

    if (tid < 128) toks[tid] = seq[(size_t)b * kT + tid];
    __syncthreads();

    const int wm = (wid & 1) * 64;
    const int wn = (wid >> 1) * 32;

    float acc[4][4][4];
#pragma unroll
    for (int i = 0; i < 4; i++)
#pragma unroll
        for (int j = 0; j < 4; j++)
#pragma unroll
            for (int q = 0; q < 4; q++) acc[i][j][q] = 0.f;

    auto issue_chunk = [&](int kc, int stg) {
#pragma unroll
        for (int i = 0; i < 12; i++) {
            int idx = i * 256 + tid;
            uint32_t dst;
            const __half* src;
            if (idx < 2048) {
                int mat = idx >> 10, r = (idx >> 3) & 127, q = idx & 7;
                src = (mat ? g_emb_lo : g_emb_hi) + (size_t)toks[r] * kEmbP + kc * 64 + q * 8;
                uint32_t off = (uint32_t)(r * 128 + ((q ^ (r & 7)) * 16));
                dst = smb + stg * PC_STG + mat * 16384 + off;
            } else {
                int idxB = idx - 2048;
                int r = (idxB >> 3) & 127, q = idxB & 7;
                src = g_wt + (size_t)(n0 + r) * kEmbP + kc * 64 + q * 8;
                uint32_t off = (uint32_t)(r * 128 + ((q ^ (r & 7)) * 16));
                dst = smb + stg * PC_STG + 32768 + off;
            }
            CP_ASYNC16(dst, src);
        }
        CP_COMMIT();
    };

    issue_chunk(0, 0);

    const int la7 = lane & 7;
    const int arow_off = (lane >> 3) & 1;
    const int akseg   = (lane >> 4) & 1;
    const int brow_off = (lane >> 4) & 1;
    const int bkseg   = (lane >> 3) & 1;

    for (int kc = 0; kc < 5; kc++) {
        CP_WAIT0();
        __syncthreads();
        if (kc < 4) issue_chunk(kc + 1, (kc + 1) & 1);

        const uint32_t base = smb + (kc & 1) * PC_STG;
#pragma unroll
        for (int ks = 0; ks < 4; ks++) {
            uint32_t ahi[4][4], alo[4][4], bb[2][4];
#pragma unroll
            for (int mf = 0; mf < 4; mf++) {
                int row = wm + mf * 16 + la7 + arow_off * 8;
                uint32_t off = (uint32_t)(row * 128 + ks * 32 + akseg * 16);
                off ^= (uint32_t)((row & 7) * 16);
                LDMATRIX_X4(ahi[mf][0], ahi[mf][1], ahi[mf][2], ahi[mf][3], base + off);
                LDMATRIX_X4(alo[mf][0], alo[mf][1], alo[mf][2], alo[mf][3], base + 16384 + off);
            }
#pragma unroll
            for (int p = 0; p < 2; p++) {
                int row = wn + p * 16 + la7 + brow_off * 8;
                uint32_t off = (uint32_t)(row * 128 + ks * 32 + bkseg * 16);
                off ^= (uint32_t)((row & 7) * 16);
                LDMATRIX_X4(bb[p][0], bb[p][1], bb[p][2], bb[p][3], base + 32768 + off);
            }
#pragma unroll
            for (int mf = 0; mf < 4; mf++)
#pragma unroll
                for (int nf = 0; nf < 4; nf++) {
                    const int p = nf >> 1, s = (nf & 1) * 2;
                    float* c = acc[mf][nf];
                    MMA_F16(c[0], c[1], c[2], c[3],
                            ahi[mf][0], ahi[mf][1], ahi[mf][2], ahi[mf][3],
                            bb[p][s], bb[p][s + 1]);
                    MMA_F16(c[0], c[1], c[2], c[3],
                            alo[mf][0], alo[mf][1], alo[mf][2], alo[mf][3],
                            bb[p][s], bb[p][s + 1]);
                }
        }
    }

    __syncthreads();
    float* zs = (float*)smp;
    {
        const int cr = lane >> 2, cc = (lane & 3) * 2;
#pragma unroll
        for (int mf = 0; mf < 4; mf++)
#pragma unroll
            for (int nf = 0; nf < 4; nf++) {
                int row = wm + mf * 16 + cr;
                int col = wn + nf * 8 + cc;
                *(float2*)&zs[row * 128 + col]       = make_float2(acc[mf][nf][0], acc[mf][nf][1]);
                *(float2*)&zs[(row + 8) * 128 + col] = make_float2(acc[mf][nf][2], acc[mf][nf][3]);
            }
    }
    __syncthreads();

    const int cseg = tid & 31;
    float4 bv = __ldg((const float4*)(bias + n0 + cseg * 4));
#pragma unroll
    for (int i = 0; i < 16; i++) {
        int r = i * 8 + (tid >> 5);
        float4 v = *(const float4*)&zs[r * 128 + cseg * 4];
        __half2 p0 = __floats2half2_rn(v.x + bv.x, v.y + bv.y);
        __half2 p1 = __floats2half2_rn(v.z + bv.z, v.w + bv.w);
        uint2 pk = make_uint2(*(uint32_t*)&p0, *(uint32_t*)&p1);
        *(uint2*)(g_zpre_h + ((size_t)b * kT + r) * kG + n0 + cseg * 4) = pk;
    }
}

// ---------------- mma.sync LSTM step with PDL overlap ----------------
// grid (16 nt, 8 mt) = 128 CTAs, 256 thr, launch_bounds(256,2) for co-residency.
// Pre-wait: B chunks 0,1 + zpre(t>0) + seq.  griddepcontrol.wait -> dependent reads.
// Commits: B0,B1,A0,A1, then combined C2..C7 (deferred) -> waits = R16's 1/0 pattern.
#define ST_STG 24576
#define ST_DYN 73728

extern "C" __global__ void __launch_bounds__(256, 2) step_mma_kernel(
    int t,
    const int* __restrict__ seq,
    const float* __restrict__ hprev_f32, int hstride,
    const float* __restrict__ c0,
    float* __restrict__ out)
{
    extern __shared__ __align__(1024) char smp[];
    const uint32_t smb = smem_u32(smp);

    const int tid = threadIdx.x;
    const int wid = tid >> 5, lane = tid & 31;
    const int nt = blockIdx.x, mt = blockIdx.y;
    const int b0 = mt * 64;
    const int n0 = nt * 128;
    const int u0g = nt * 32;

    const __half* srcB = g_u + (size_t)n0 * kUnits;

    // ---- PRE-WAIT: B chunks 0,1 (static) ----
    auto issue_B = [&](int kc, int stg) {
#pragma unroll
        for (int i = 0; i < 4; i++) {
            int idx = i * 256 + tid;       // 0..1023
            int r = idx >> 3, q = idx & 7;
            const __half* src = srcB + (size_t)r * kUnits + kc * 64 + q * 8;
            uint32_t off = (uint32_t)(r * 128 + ((q ^ (r & 7)) * 16));
            CP_ASYNC16(smb + stg * ST_STG + 8192 + off, src);
        }
        CP_COMMIT();
    };
    issue_B(0, 0);
    issue_B(1, 1);

    // epilogue cell map: 2 rows x 4 consecutive units
    const int ug = tid & 7;
    const int rg = tid >> 3;
    const int ub = u0g + ug * 4;
    float4 creg4[2], zpf4[2][4];
    int seqv[2];
    auto prefetch_z = [&]() {
#pragma unroll
        for (int it = 0; it < 2; it++) {
            int b = b0 + rg * 2 + it;
            const __half* zp = g_zpre_h + ((size_t)b * kT + t) * kG;
#pragma unroll
            for (int g = 0; g < 4; g++) {
                uint2 raw = __ldg((const uint2*)(zp + g * kUnits + ub));
                __half2 h0v = *(__half2*)&raw.x;
                __half2 h1v = *(__half2*)&raw.y;
                zpf4[it][g] = make_float4(__low2float(h0v), __high2float(h0v),
                                          __low2float(h1v), __high2float(h1v));
            }
            seqv[it] = __ldg(seq + (size_t)b * kT + t);
        }
    };
    if (t > 0) prefetch_z();   // zpre static for t>0 (precompute finished before t-1 ran)

    // ---- dependency fence: prior step's g_hb/g_c/out now visible ----
    GRIDDEP_WAIT();
    GRIDDEP_LAUNCH();          // let step t+1 start its pre-wait phase ASAP

    if (t == 0) prefetch_z();  // t=0: zpre write (precompute) is the prior kernel
    {
        const float* cin = (t == 0) ? c0 : g_c;
#pragma unroll
        for (int it = 0; it < 2; it++) {
            int b = b0 + rg * 2 + it;
            creg4[it] = __ldg((const float4*)(cin + (size_t)b * kUnits + ub));
        }
    }

    const __half* srcA = g_hb[(t + 1) & 1] + (size_t)b0 * kUnits;
    auto issue_A = [&](int kc, int stg) {
#pragma unroll
        for (int i = 0; i < 2; i++) {
            int idx = i * 256 + tid;       // 0..511
            int r = idx >> 3, q = idx & 7;
            const __half* src = srcA + (size_t)r * kUnits + kc * 64 + q * 8;
            uint32_t off = (uint32_t)(r * 128 + ((q ^ (r & 7)) * 16));
            CP_ASYNC16(smb + stg * ST_STG + off, src);
        }
        CP_COMMIT();
    };
    auto issue_AB = [&](int kc, int stg) {
#pragma unroll
        for (int i = 0; i < 6; i++) {
            int idx = i * 256 + tid;       // 0..1535
            uint32_t dst;
            const __half* src;
            if (idx < 512) {
                int r = idx >> 3, q = idx & 7;
                src = srcA + (size_t)r * kUnits + kc * 64 + q * 8;
                dst = smb + stg * ST_STG + (uint32_t)(r * 128 + ((q ^ (r & 7)) * 16));
            } else {
                int idxB = idx - 512;
                int r = idxB >> 3, q = idxB & 7;
                src = srcB + (size_t)r * kUnits + kc * 64 + q * 8;
                dst = smb + stg * ST_STG + 8192 + (uint32_t)(r * 128 + ((q ^ (r & 7)) * 16));
            }
            CP_ASYNC16(dst, src);
        }
        CP_COMMIT();
    };

    issue_A(0, 0);
    issue_A(1, 1);

    const int wm = (wid & 1) * 32;
    const int wn = (wid >> 1) * 32;

    float acc[2][4][4];
#pragma unroll
    for (int i = 0; i < 2; i++)
#pragma unroll
        for (int j = 0; j < 4; j++)
#pragma unroll
            for (int q = 0; q < 4; q++) acc[i][j][q] = 0.f;

    const int la7 = lane & 7;
    const int arow_off = (lane >> 3) & 1;
    const int akseg   = (lane >> 4) & 1;
    const int brow_off = (lane >> 4) & 1;
    const int bkseg   = (lane >> 3) & 1;

    for (int kc = 0; kc < 8; kc++) {
        if (kc < 7) { CP_WAIT1(); } else { CP_WAIT0(); }
        __syncthreads();
        if (kc < 6) issue_AB(kc + 2, (kc + 2) % 3);

        const uint32_t base = smb + (kc % 3) * ST_STG;
#pragma unroll
        for (int ks = 0; ks < 4; ks++) {
            uint32_t aa[2][4], bb[2][4];
#pragma unroll
            for (int mf = 0; mf < 2; mf++) {
                int row = wm + mf * 16 + la7 + arow_off * 8;
                uint32_t off = (uint32_t)(row * 128 + ks * 32 + akseg * 16);
                off ^= (uint32_t)((row & 7) * 16);
                LDMATRIX_X4(aa[mf][0], aa[mf][1], aa[mf][2], aa[mf][3], base + off);
            }
#pragma unroll
            for (int p = 0; p < 2; p++) {
                int row = wn + p * 16 + la7 + brow_off * 8;
                uint32_t off = (uint32_t)(row * 128 + ks * 32 + bkseg * 16);
                off ^= (uint32_t)((row & 7) * 16);
                LDMATRIX_X4(bb[p][0], bb[p][1], bb[p][2], bb[p][3], base + 8192 + off);
            }
#pragma unroll
            for (int mf = 0; mf < 2; mf++)
#pragma unroll
                for (int nf = 0; nf < 4; nf++) {
                    const int p = nf >> 1, s = (nf & 1) * 2;
                    float* c = acc[mf][nf];
                    MMA_F16(c[0], c[1], c[2], c[3],
                            aa[mf][0], aa[mf][1], aa[mf][2], aa[mf][3],
                            bb[p][s], bb[p][s + 1]);
                }
        }
    }

    // ---- stage z to smem: 64x128 f32 = 32KB ----
    __syncthreads();
    float* zs = (float*)smp;
    {
        const int cr = lane >> 2, cc = (lane & 3) * 2;
#pragma unroll
        for (int mf = 0; mf < 2; mf++)
#pragma unroll
            for (int nf = 0; nf < 4; nf++) {
                int row = wm + mf * 16 + cr;
                int col = wn + nf * 8 + cc;
                *(float2*)&zs[row * 128 + col]       = make_float2(acc[mf][nf][0], acc[mf][nf][1]);
                *(float2*)&zs[(row + 8) * 128 + col] = make_float2(acc[mf][nf][2], acc[mf][nf][3]);
            }
    }
    __syncthreads();

    // ---- fused LSTM epilogue (vectorized, + finalize at t = T-1) ----
    __half* dsth = g_hb[t & 1];
    const bool lastt = (t == kT - 1);
    float* hfin = out + (size_t)kB * kT * kUnits;
    float* cfin = hfin + (size_t)kB * kUnits;
#pragma unroll
    for (int it = 0; it < 2; it++) {
        int rb = rg * 2 + it;
        int b = b0 + rb;
        float4 zq[4];
#pragma unroll
        for (int j = 0; j < 4; j++)
            zq[j] = *(const float4*)&zs[rb * 128 + ug * 16 + j * 4];

        float4 hv, cv;
        float* hp = (float*)&hv;
        float* cp = (float*)&cv;
        const float* cold4 = (const float*)&creg4[it];
#pragma unroll
        for (int j = 0; j < 4; j++) {
            float zi = zq[j].x + ((const float*)&zpf4[it][0])[j];
            float zf = zq[j].y + ((const float*)&zpf4[it][1])[j];
            float zg = zq[j].z + ((const float*)&zpf4[it][2])[j];
            float zo = zq[j].w + ((const float*)&zpf4[it][3])[j];
            float ig = fast_sig(zi);
            float fg = fast_sig(zf);
            float og = fast_sig(zo);
            float cnew = fmaf(fg, cold4[j], ig * fast_tanh(zg));
            hp[j] = og * fast_tanh(cnew);
            cp[j] = cnew;
        }
        if (seqv[it] == 0) {
            cv = creg4[it];
            hv = __ldg((const float4*)(hprev_f32 + (size_t)b * hstride + ub));
        }
        *(float4*)(g_c + (size_t)b * kUnits + ub) = cv;
        *(float4*)(out + (size_t)b * (kT * kUnits) + (size_t)t * kUnits + ub) = hv;
        __half2 h01 = __floats2half2_rn(hv.x, hv.y);
        __half2 h23 = __floats2half2_rn(hv.z, hv.w);
        uint2 hpk = make_uint2(*(uint32_t*)&h01, *(uint32_t*)&h23);
        *(uint2*)(dsth + (size_t)b * kUnits + ub) = hpk;
        if (lastt) {
            *(float4*)(hfin + (size_t)b * kUnits + ub) = hv;
            *(float4*)(cfin + (size_t)b * kUnits + ub) = cv;
        }
    }
}

// ---------------- host ----------------
extern "C" void kernel_launch(void* const* d_in, const int* in_sizes, int n_in,
                              void* d_out, int out_size)
{
    const int*   seq  = (const int*)d_in[0];
    const float* h0   = (const float*)d_in[1];
    const float* c0   = (const float*)d_in[2];
    const float* emb  = (const float*)d_in[3];
    const float* W    = (const float*)d_in[4];
    const float* Umat = (const float*)d_in[5];
    const float* bias = (const float*)d_in[6];
    float* out = (float*)d_out;

    static int configured = 0;
    static int pdl_ok = 1;
    if (!configured) {
        cudaFuncSetAttribute(precompute_mma_kernel, cudaFuncAttributeMaxDynamicSharedMemorySize, PC_DYN);
        cudaFuncSetAttribute(step_mma_kernel, cudaFuncAttributeMaxDynamicSharedMemorySize, ST_DYN);
        configured = 1;
    }

    const int embBlocks = (kVocab + 7) / 8;
    prep_kernel<<<kG + 8 + kG + embBlocks, 128>>>(Umat, h0, W, emb);

    precompute_mma_kernel<<<dim3(16, kB), 256, PC_DYN>>>(seq, bias);

    for (int t = 0; t < kT; t++) {
        const float* hprev = t ? (out + (size_t)(t - 1) * kUnits) : h0;
        int hstride = t ? (kT * kUnits) : kUnits;
        bool done = false;
        if (pdl_ok) {
            cudaLaunchConfig_t cfg = {};
            cfg.gridDim = dim3(16, 8, 1);
            cfg.blockDim = dim3(256, 1, 1);
            cfg.dynamicSmemBytes = ST_DYN;
            cfg.stream = 0;
            cudaLaunchAttribute attrs[1];
            attrs[0].id = cudaLaunchAttributeProgrammaticStreamSerialization;
            attrs[0].val.programmaticStreamSerializationAllowed = 1;
            cfg.attrs = attrs;
            cfg.numAttrs = 1;
            cudaError_t rc = cudaLaunchKernelEx(&cfg, step_mma_kernel,
                                                t, seq, hprev, hstride, c0, out);
            if (rc == cudaSuccess) done = true;
            else { cudaGetLastError(); pdl_ok = 0; }
        }
        if (!done)
            step_mma_kernel<<<dim3(16, 8), 256, ST_DYN>>>(t, seq, hprev, hstride, c0, out);
    }
}